// round 2
// baseline (speedup 1.0000x reference)
#include <cuda_runtime.h>
#include <cstdint>

#define N_TEMPL 4
#define N_RES   768
#define NCH     64
#define NCOLS   89   // 88 real columns + 1 zero column for "no distogram bin"

// Shared memory budget:
//   Wt    : 89*64*4  = 22784 B
//   sUV   : 768*16   = 12288 B  (uvx, uvy, uvz, pb2d)
//   sMeta : 768*16   = 12288 B  (fm2, bin_col_float_idx, aaj_col_float_idx, -)
//   row constants    : ~96 B
// total ~47.5 KB static shared (< 48 KB static limit).

__global__ __launch_bounds__(256) void tpe_kernel(
    const float* __restrict__ pos,      // [T,768,37,3]
    const float* __restrict__ pb,       // [T,768,3]
    const float* __restrict__ pbm,      // [T,768]
    const float* __restrict__ aam,      // [T,768,37]
    const int*   __restrict__ aatype,   // [T,768]
    const float* __restrict__ lw,       // [64,88] row-major (o-major)
    const float* __restrict__ lb,       // [64]
    float* __restrict__ out)            // [T,768,768,64]
{
    __shared__ float  Wt[NCOLS * NCH];
    __shared__ float4 sUV[N_RES];
    __shared__ float4 sMeta[N_RES];
    __shared__ float  sM[9];            // frame rotation (row-major), rv = sM @ diff
    __shared__ float  sCa[3];
    __shared__ float  sPb[3];
    __shared__ float  sPbmI;
    __shared__ float  sFmI;
    __shared__ int    sAaI;

    const float EPS = 1e-6f;
    const int t = blockIdx.x / N_RES;
    const int i = blockIdx.x % N_RES;
    const int tid = threadIdx.x;

    // ---------------- Phase 0: stage W transposed, zero col 88, build frame ----
    #pragma unroll 4
    for (int idx = tid; idx < 88 * NCH; idx += 256) {
        int c = idx >> 6, o = idx & 63;
        Wt[c * NCH + o] = lw[o * 88 + c];
    }
    if (tid < NCH) Wt[88 * NCH + tid] = 0.0f;

    if (tid == 0) {
        const float* pr = pos + ((size_t)(t * N_RES + i) * 37) * 3;
        float nx0 = pr[0], nx1 = pr[1], nx2 = pr[2];     // N
        float ca0 = pr[3], ca1 = pr[4], ca2 = pr[5];     // CA
        float cc0 = pr[6], cc1 = pr[7], cc2 = pr[8];     // C
        float n0 = nx0 - ca0, n1 = nx1 - ca1, n2 = nx2 - ca2;
        float c0 = cc0 - ca0, c1v = cc1 - ca1, c2v = cc2 - ca2;

        float d2xy = c0 * c0 + c1v * c1v;
        float norm1 = sqrtf(EPS + d2xy);
        float s1 = -c1v / norm1, co1 = c0 / norm1;
        float norm2 = sqrtf(EPS + d2xy + c2v * c2v);
        float s2 = c2v / norm2, co2 = sqrtf(d2xy) / norm2;

        // c2 @ c1
        float r00 = co2 * co1, r01 = -co2 * s1, r02 = s2;
        float r10 = s1,        r11 = co1,       r12 = 0.0f;
        float r20 = -s2 * co1, r21 = s2 * s1,   r22 = co2;

        float nyp = r10 * n0 + r11 * n1 + r12 * n2;
        float nzp = r20 * n0 + r21 * n1 + r22 * n2;
        float norm3 = sqrtf(EPS + nyp * nyp + nzp * nzp);
        float sn = -nzp / norm3, cn = nyp / norm3;

        // M = nr @ (c2 @ c1);  rigid_vec = M @ diff  (reference transposes twice)
        sM[0] = r00; sM[1] = r01; sM[2] = r02;
        sM[3] = cn * r10 - sn * r20; sM[4] = cn * r11 - sn * r21; sM[5] = cn * r12 - sn * r22;
        sM[6] = sn * r10 + cn * r20; sM[7] = sn * r11 + cn * r21; sM[8] = sn * r12 + cn * r22;

        sCa[0] = ca0; sCa[1] = ca1; sCa[2] = ca2;
        const float* pbi = pb + (size_t)(t * N_RES + i) * 3;
        sPb[0] = pbi[0]; sPb[1] = pbi[1]; sPb[2] = pbi[2];
        sPbmI = pbm[t * N_RES + i];
        const float* ami = aam + (size_t)(t * N_RES + i) * 37;
        sFmI = ami[0] * ami[1] * ami[2];
        sAaI = aatype[t * N_RES + i];
    }
    __syncthreads();

    // ---------------- Phase 1: per-j scalars (3 j's per thread) ---------------
    {
        const float m0 = sM[0], m1 = sM[1], m2 = sM[2];
        const float m3 = sM[3], m4 = sM[4], m5 = sM[5];
        const float m6 = sM[6], m7 = sM[7], m8 = sM[8];
        const float cai0 = sCa[0], cai1 = sCa[1], cai2 = sCa[2];
        const float pbi0 = sPb[0], pbi1 = sPb[1], pbi2 = sPb[2];
        const float pbmi = sPbmI, fmi = sFmI;

        for (int j = tid; j < N_RES; j += 256) {
            // distogram bin from pseudo-beta distance (match reference FP ordering)
            const float* pbj = pb + (size_t)(t * N_RES + j) * 3;
            float dx = __fadd_rn(pbi0, -pbj[0]);
            float dy = __fadd_rn(pbi1, -pbj[1]);
            float dz = __fadd_rn(pbi2, -pbj[2]);
            float dsq = __fadd_rn(__fadd_rn(__fmul_rn(dx, dx), __fmul_rn(dy, dy)),
                                  __fmul_rn(dz, dz));
            int k = (int)floorf((sqrtf(dsq) - 3.25f) * 0.8f);
            k = min(max(k, -1), 38);
            int bin = -1;
            int clo = max(k - 1, 0), chi = min(k + 1, 38);
            #pragma unroll
            for (int c = 0; c < 3; ++c) {
                int cand = clo + c;
                if (cand > chi) break;
                float lbv = 3.25f + (float)cand * 1.25f;  lbv = lbv * lbv;
                float ubv = (cand == 38) ? 1e8f
                           : (3.25f + (float)(cand + 1) * 1.25f) *
                             (3.25f + (float)(cand + 1) * 1.25f);
                if (dsq > lbv && dsq < ubv) { bin = cand; break; }
            }

            // rigid vec + unit vector
            const float* pj = pos + ((size_t)(t * N_RES + j) * 37 + 1) * 3; // CA_j
            float ddx = pj[0] - cai0, ddy = pj[1] - cai1, ddz = pj[2] - cai2;
            float rvx = m0 * ddx + m1 * ddy + m2 * ddz;
            float rvy = m3 * ddx + m4 * ddy + m5 * ddz;
            float rvz = m6 * ddx + m7 * ddy + m8 * ddz;
            float inv = 1.0f / sqrtf(EPS + (rvx * rvx + rvy * rvy + rvz * rvz));
            float uvx = rvx * inv, uvy = rvy * inv, uvz = rvz * inv;

            const float* amj = aam + (size_t)(t * N_RES + j) * 37;
            float fm2 = fmi * (amj[0] * amj[1] * amj[2]);
            float pb2 = pbmi * pbm[t * N_RES + j];

            sUV[j] = make_float4(uvx, uvy, uvz, pb2);
            int binIdx = ((bin < 0) ? 88 : bin) * NCH;
            int aajIdx = (40 + aatype[t * N_RES + j]) * NCH;
            sMeta[j] = make_float4(fm2, __int_as_float(binIdx),
                                   __int_as_float(aajIdx), 0.0f);
        }
    }
    __syncthreads();

    // ---------------- Phase 2: 16 threads x 4 channels per j ------------------
    const int oq = tid & 15;          // channel quad: o = 4*oq .. 4*oq+3
    const int jl = tid >> 4;          // 16 j's per iteration
    const int ob = oq * 4;

    float4 rowb, w39v, w84v, w85v, w86v, bv;
    {
        const float4 wai = *(const float4*)&Wt[(62 + sAaI) * NCH + ob];
        const float4 w87 = *(const float4*)&Wt[87 * NCH + ob];
        rowb = make_float4(wai.x + w87.x, wai.y + w87.y, wai.z + w87.z, wai.w + w87.w);
        w39v = *(const float4*)&Wt[39 * NCH + ob];
        w84v = *(const float4*)&Wt[84 * NCH + ob];
        w85v = *(const float4*)&Wt[85 * NCH + ob];
        w86v = *(const float4*)&Wt[86 * NCH + ob];
        bv   = *(const float4*)&lb[ob];
    }

    float* orow = out + ((size_t)(t * N_RES + i) * N_RES) * NCH;

    #pragma unroll 4
    for (int jb = 0; jb < N_RES; jb += 16) {
        int j = jb + jl;
        float4 uvp = sUV[j];
        float4 mt  = sMeta[j];
        int bo = __float_as_int(mt.y);
        int ao = __float_as_int(mt.z);
        float4 wb = *(const float4*)&Wt[bo + ob];
        float4 wa = *(const float4*)&Wt[ao + ob];

        float4 r;
        {
            float s = rowb.x + wb.x + wa.x;
            s = fmaf(uvp.w, w39v.x, s);
            s = fmaf(uvp.x, w84v.x, s);
            s = fmaf(uvp.y, w85v.x, s);
            s = fmaf(uvp.z, w86v.x, s);
            r.x = fmaf(mt.x, s, bv.x);
        }
        {
            float s = rowb.y + wb.y + wa.y;
            s = fmaf(uvp.w, w39v.y, s);
            s = fmaf(uvp.x, w84v.y, s);
            s = fmaf(uvp.y, w85v.y, s);
            s = fmaf(uvp.z, w86v.y, s);
            r.y = fmaf(mt.x, s, bv.y);
        }
        {
            float s = rowb.z + wb.z + wa.z;
            s = fmaf(uvp.w, w39v.z, s);
            s = fmaf(uvp.x, w84v.z, s);
            s = fmaf(uvp.y, w85v.z, s);
            s = fmaf(uvp.z, w86v.z, s);
            r.z = fmaf(mt.x, s, bv.z);
        }
        {
            float s = rowb.w + wb.w + wa.w;
            s = fmaf(uvp.w, w39v.w, s);
            s = fmaf(uvp.x, w84v.w, s);
            s = fmaf(uvp.y, w85v.w, s);
            s = fmaf(uvp.z, w86v.w, s);
            r.w = fmaf(mt.x, s, bv.w);
        }

        *(float4*)&orow[(size_t)j * NCH + ob] = r;
    }
}

extern "C" void kernel_launch(void* const* d_in, const int* in_sizes, int n_in,
                              void* d_out, int out_size) {
    const float* pos    = (const float*)d_in[0];  // [4,768,37,3]
    const float* pb     = (const float*)d_in[1];  // [4,768,3]
    const float* pbmask = (const float*)d_in[2];  // [4,768]
    const float* aamask = (const float*)d_in[3];  // [4,768,37]
    const int*   aatype = (const int*)  d_in[4];  // [4,768]
    const float* lw     = (const float*)d_in[5];  // [64,88]
    const float* lb     = (const float*)d_in[6];  // [64]
    float* out = (float*)d_out;

    dim3 grid(N_TEMPL * N_RES);
    tpe_kernel<<<grid, 256>>>(pos, pb, pbmask, aamask, aatype, lw, lb, out);
}